// round 7
// baseline (speedup 1.0000x reference)
#include <cuda_runtime.h>

#define LROW 16384
#define N1 8199
#define N2 4107
#define N3 2061
#define N4 1038
#define ROWS_MAX 2048

// global scratch row strides (floats, 16B-multiple)
#define S1 8200
#define S2 4112
#define S3 2064
#define S4 1040

__device__ float g_d1[(size_t)ROWS_MAX * S1];
__device__ float g_d2[(size_t)ROWS_MAX * S2];
__device__ float g_d3[(size_t)ROWS_MAX * S3];
__device__ float g_d4[(size_t)ROWS_MAX * S4];
__device__ float g_a4[(size_t)ROWS_MAX * S4];
__device__ float g_thr[ROWS_MAX];

// smem: fwd: A1[0,8208) A2[8208,12320), A3 overlays A1.
//       inv: REC[0,8208) R3[8208,12320), R4 overlays REC.
#define SM_FLOATS 12320
#define SM_BYTES  (SM_FLOATS * 4)
#define OFF_HI    8208

#define HLIT { \
    0.05441584224308161f,    0.3128715909144659f,    0.6756307362980128f, \
    0.5853546836548691f,    -0.015829105256023893f, -0.2840155429624281f, \
    0.00047248457399797254f, 0.128747426620186f,    -0.01736930100202211f, \
   -0.04408825393106472f,    0.013981027917015516f,  0.008746094047015655f, \
   -0.00487035299301066f,   -0.0003917403729959771f, 0.0006754494059985568f, \
   -0.00011747678400228192f }

__device__ __forceinline__ float softthr(float v, float thr) {
    float av = fabsf(v) - thr;
    return av > 0.f ? copysignf(av, v) : 0.f;
}

// ---- 8-wide DWT pass: vector region [0, vend), scalar tail [vend, nout) ----
__device__ __forceinline__ void dwt_pass8(const float* __restrict__ xin, int n,
                                          int vend, int nout,
                                          float* __restrict__ ca,
                                          float* __restrict__ cd,
                                          int tid)
{
    const float H[16] = HLIT;
    for (int b = 8 * tid; b < vend; b += 2048) {
        int lo = 2 * b - 16;
        float w[32];
        if (lo >= 0) {
            #pragma unroll
            for (int j = 0; j < 8; j++) {
                float4 v = *reinterpret_cast<const float4*>(xin + lo + 4 * j);
                w[4*j+0]=v.x; w[4*j+1]=v.y; w[4*j+2]=v.z; w[4*j+3]=v.w;
            }
        } else {                                  // only b==0
            #pragma unroll
            for (int j = 0; j < 32; j++) {
                int m = lo + j;
                m = (m < 0) ? (-1 - m) : m;
                w[j] = xin[m];
            }
        }
        float ao[8], dd[8];
        #pragma unroll
        for (int r = 0; r < 8; r++) {
            float a = 0.f, d = 0.f;
            #pragma unroll
            for (int t = 0; t < 16; t++) {
                float xv = w[2*r + t + 2];
                a = fmaf(H[t], xv, a);
                d = fmaf((t & 1) ? -H[15-t] : H[15-t], xv, d);
            }
            ao[r] = a; dd[r] = d;
        }
        *reinterpret_cast<float4*>(ca + b)     = make_float4(ao[0],ao[1],ao[2],ao[3]);
        *reinterpret_cast<float4*>(ca + b + 4) = make_float4(ao[4],ao[5],ao[6],ao[7]);
        *reinterpret_cast<float4*>(cd + b)     = make_float4(dd[0],dd[1],dd[2],dd[3]);
        *reinterpret_cast<float4*>(cd + b + 4) = make_float4(dd[4],dd[5],dd[6],dd[7]);
    }
    int k = vend + tid;                            // tail: one output per thread
    if (k < nout) {
        float a = 0.f, d = 0.f;
        #pragma unroll
        for (int t = 0; t < 16; t++) {
            int m = 2 * k + t - 14;
            m = (m >= n) ? (2 * n - 1 - m) : m;    // high reflect only (k large)
            float xv = xin[m];
            a = fmaf(H[t], xv, a);
            d = fmaf((t & 1) ? -H[15-t] : H[15-t], xv, d);
        }
        ca[k] = a; cd[k] = d;
    }
}

// ============ K_fwd: level-1 DWT + exact median + DWT levels 2-4 ============
__global__ void __launch_bounds__(256, 3)
k_fwd(const float* __restrict__ x, float* __restrict__ d1g,
      float* __restrict__ d2g, float* __restrict__ d3g,
      float* __restrict__ d4g, float* __restrict__ a4g,
      float* __restrict__ thr_out)
{
    extern __shared__ float sm[];
    float* A1 = sm;              // flat 8200
    float* A2 = sm + OFF_HI;     // flat 4108
    float* A3 = sm;              // overlays dead A1

    __shared__ int      s_hist[4][256];
    __shared__ unsigned s_pref;
    __shared__ int      s_rank;

    const int tid = threadIdx.x, lane = tid & 31, warp = tid >> 5;
    const int row = blockIdx.x;
    const float* xin = x + (size_t)row * LROW;
    float* pd1 = d1g + (size_t)row * S1;
    float* pd2 = d2g + (size_t)row * S2;
    float* pd3 = d3g + (size_t)row * S3;
    float* pd4 = d4g + (size_t)row * S4;
    float* pa4 = a4g + (size_t)row * S4;

    // pre-clear all 4 round-histograms once
    #pragma unroll
    for (int rr = 0; rr < 4; rr++) s_hist[rr][tid] = 0;
    if (tid == 0) { s_pref = 0u; s_rank = (N1 - 1) / 2; }

    const float H[16] = HLIT;

    // ---- level 1: x -> A1 smem + d1 (regs + global), 8 consecutive / chunk ----
    float dreg[32];
    #pragma unroll
    for (int c = 0; c < 4; c++) {
        int b = 2048 * c + 8 * tid;          // vector region covers [0, 8192)
        int lo = 2 * b - 16;
        float w[32];
        if (lo >= 0) {                        // window end 2b+16 <= 16384 always
            #pragma unroll
            for (int j = 0; j < 8; j++) {
                float4 v = *reinterpret_cast<const float4*>(xin + lo + 4 * j);
                w[4*j+0]=v.x; w[4*j+1]=v.y; w[4*j+2]=v.z; w[4*j+3]=v.w;
            }
        } else {                              // only c==0, tid==0
            #pragma unroll
            for (int j = 0; j < 32; j++) {
                int m = lo + j;
                m = (m < 0) ? (-1 - m) : m;
                w[j] = xin[m];
            }
        }
        float ao[8];
        #pragma unroll
        for (int r = 0; r < 8; r++) {
            float a = 0.f, d = 0.f;
            #pragma unroll
            for (int t = 0; t < 16; t++) {
                float xv = w[2*r + t + 2];
                a = fmaf(H[t], xv, a);
                d = fmaf((t & 1) ? -H[15-t] : H[15-t], xv, d);
            }
            ao[r] = a;
            dreg[8*c + r] = d;
        }
        *reinterpret_cast<float4*>(A1 + b)      = make_float4(ao[0],ao[1],ao[2],ao[3]);
        *reinterpret_cast<float4*>(A1 + b + 4)  = make_float4(ao[4],ao[5],ao[6],ao[7]);
        *reinterpret_cast<float4*>(pd1 + b)     = make_float4(dreg[8*c],dreg[8*c+1],dreg[8*c+2],dreg[8*c+3]);
        *reinterpret_cast<float4*>(pd1 + b + 4) = make_float4(dreg[8*c+4],dreg[8*c+5],dreg[8*c+6],dreg[8*c+7]);
    }
    // tail k = 8192..8198, distributed to threads 0-6
    float dtail = 0.f;
    if (tid < 7) {
        int k = 8192 + tid;
        float a = 0.f, d = 0.f;
        #pragma unroll
        for (int t = 0; t < 16; t++) {
            int m = 2 * k + t - 14;
            if (m >= LROW) m = 2 * LROW - 1 - m;
            float xv = xin[m];
            a = fmaf(H[t], xv, a);
            d = fmaf((t & 1) ? -H[15-t] : H[15-t], xv, d);
        }
        A1[k] = a; pd1[k] = d; dtail = d;
    }
    __syncthreads();

    // ---- exact median of |d1|: 4-round radix select, 2 barriers/round ----
    for (int b3 = 3; b3 >= 0; --b3) {
        const unsigned pref = s_pref;
        const int rank = s_rank;
        const int sh = b3 * 8;
        int* hist = s_hist[b3];
        #pragma unroll
        for (int j = 0; j < 32; j++) {
            unsigned u = __float_as_uint(fabsf(dreg[j]));
            bool mt = (b3 == 3) || ((u >> (sh + 8)) == pref);
            if (__any_sync(0xffffffffu, mt)) {
                unsigned bin = (u >> sh) & 255u;
                unsigned key = mt ? bin : 256u;
                unsigned grp = __match_any_sync(0xffffffffu, key);
                if (mt && lane == (__ffs(grp) - 1))
                    atomicAdd(&hist[bin], __popc(grp));
            }
        }
        if (tid < 7) {
            unsigned u = __float_as_uint(fabsf(dtail));
            if ((b3 == 3) || ((u >> (sh + 8)) == pref))
                atomicAdd(&hist[(u >> sh) & 255u], 1);
        }
        __syncthreads();
        if (warp == 0) {                      // warp-0-only winner-bin reduction
            int base = lane * 8;
            int cnt[8], s = 0;
            #pragma unroll
            for (int q = 0; q < 8; q++) { cnt[q] = hist[base + q]; s += cnt[q]; }
            int incl = s;
            #pragma unroll
            for (int o = 1; o < 32; o <<= 1) {
                int t2 = __shfl_up_sync(0xffffffffu, incl, o);
                if (lane >= o) incl += t2;
            }
            int excl = incl - s;
            if (rank >= excl && rank < incl) {
                int acc = excl;
                #pragma unroll
                for (int q = 0; q < 8; q++) {
                    if (rank < acc + cnt[q]) {
                        s_pref = (pref << 8) | (unsigned)(base + q);
                        s_rank = rank - acc;
                        break;
                    }
                    acc += cnt[q];
                }
            }
        }
        __syncthreads();
    }
    if (tid == 0) {
        float med = __uint_as_float(s_pref);
        thr_out[row] = (med / 0.6745f) * 4.4054649f;   // * sqrt(2 ln 16384)
    }

    // ---- levels 2-4 (A1 already visible via median barriers) ----
    dwt_pass8(A1, N1, 4096, N2, A2,  pd2, tid);   __syncthreads();
    dwt_pass8(A2, N2, 2048, N3, A3,  pd3, tid);   __syncthreads();  // A3 overlays A1
    dwt_pass8(A3, N3, 1024, N4, pa4, pd4, tid);
}

// ---------- idwt core: 4 pairs from a[12], d[12] ----------
__device__ __forceinline__ void idwt4(const float* a, const float* d, float* o) {
    const float H[16] = HLIT;
    #pragma unroll
    for (int pp = 0; pp < 4; pp++) {
        float e = 0.f, od = 0.f;
        #pragma unroll
        for (int s = 0; s < 8; s++) {
            e  = fmaf(H[14 - 2 * s], a[pp + s], e);
            e  = fmaf(H[2 * s + 1],  d[pp + s], e);
            od = fmaf(H[15 - 2 * s], a[pp + s], od);
            od = fmaf(-H[2 * s],     d[pp + s], od);
        }
        o[2*pp] = e; o[2*pp+1] = od;
    }
}

__device__ __forceinline__ void idwt_pass(const float* __restrict__ ca,
                                          const float* __restrict__ cd,
                                          int n, float thr,
                                          float* __restrict__ rec, int tid)
{
    int plim = n - 7;
    for (int p0 = 4 * tid; p0 < plim; p0 += 1024) {
        float a[12], d[12];
        if (p0 + 12 <= n) {
            #pragma unroll
            for (int j = 0; j < 3; j++) {
                float4 va = *reinterpret_cast<const float4*>(ca + p0 + 4 * j);
                float4 vd = *reinterpret_cast<const float4*>(cd + p0 + 4 * j);
                a[4*j] = va.x; a[4*j+1] = va.y; a[4*j+2] = va.z; a[4*j+3] = va.w;
                d[4*j] = vd.x; d[4*j+1] = vd.y; d[4*j+2] = vd.z; d[4*j+3] = vd.w;
            }
        } else {
            #pragma unroll
            for (int j = 0; j < 12; j++) {
                int q = p0 + j; if (q > n - 1) q = n - 1;
                a[j] = ca[q]; d[j] = cd[q];
            }
        }
        #pragma unroll
        for (int j = 0; j < 12; j++) d[j] = softthr(d[j], thr);
        float o[8];
        idwt4(a, d, o);
        if (p0 + 4 <= plim) {
            *reinterpret_cast<float4*>(rec + 2 * p0)     = make_float4(o[0], o[1], o[2], o[3]);
            *reinterpret_cast<float4*>(rec + 2 * p0 + 4) = make_float4(o[4], o[5], o[6], o[7]);
        } else {
            #pragma unroll
            for (int pp = 0; pp < 4; pp++)
                if (p0 + pp < plim) {
                    rec[2 * (p0 + pp)]     = o[2*pp];
                    rec[2 * (p0 + pp) + 1] = o[2*pp+1];
                }
        }
    }
}

// ============ K_inv: IDWT 4 -> 3 -> 2 -> 1, final level streams to out =======
__global__ void __launch_bounds__(256, 4)
k_inv(const float* __restrict__ a4g, const float* __restrict__ d4g,
      const float* __restrict__ d3g, const float* __restrict__ d2g,
      const float* __restrict__ d1g, const float* __restrict__ thr_arr,
      float* __restrict__ out)
{
    extern __shared__ float sm[];
    float* REC = sm;             // flat 8200
    float* R4  = sm;             // overlays REC
    float* R3  = sm + OFF_HI;    // flat 4108

    const int tid = threadIdx.x;
    const int row = blockIdx.x;
    const float thr = __ldg(thr_arr + row);
    const float* pa4 = a4g + (size_t)row * S4;
    const float* pd4 = d4g + (size_t)row * S4;
    const float* pd3 = d3g + (size_t)row * S3;
    const float* pd2 = d2g + (size_t)row * S2;
    const float* pd1 = d1g + (size_t)row * S1;
    float* orow = out + (size_t)row * LROW;

    idwt_pass(pa4, pd4, N4, thr, R4, tid);   __syncthreads();  // R4 flat 2062
    idwt_pass(R4,  pd3, N3, thr, R3, tid);   __syncthreads();  // R3 flat 4108
    idwt_pass(R3,  pd2, N2, thr, REC, tid);  __syncthreads();  // REC flat 8200
    idwt_pass(REC, pd1, N1, thr, orow, tid);                   // 16384 -> out
}

extern "C" void kernel_launch(void* const* d_in, const int* in_sizes, int n_in,
                              void* d_out, int out_size)
{
    const float* x = (const float*)d_in[0];
    float* out = (float*)d_out;
    int rows = in_sizes[0] / LROW;   // 2048

    float *d1, *d2, *d3, *d4, *a4, *thr;
    cudaGetSymbolAddress((void**)&d1, g_d1);
    cudaGetSymbolAddress((void**)&d2, g_d2);
    cudaGetSymbolAddress((void**)&d3, g_d3);
    cudaGetSymbolAddress((void**)&d4, g_d4);
    cudaGetSymbolAddress((void**)&a4, g_a4);
    cudaGetSymbolAddress((void**)&thr, g_thr);

    cudaFuncSetAttribute(k_fwd, cudaFuncAttributeMaxDynamicSharedMemorySize, SM_BYTES);
    cudaFuncSetAttribute(k_inv, cudaFuncAttributeMaxDynamicSharedMemorySize, SM_BYTES);

    k_fwd<<<rows, 256, SM_BYTES>>>(x, d1, d2, d3, d4, a4, thr);
    k_inv<<<rows, 256, SM_BYTES>>>(a4, d4, d3, d2, d1, thr, out);
}